// round 7
// baseline (speedup 1.0000x reference)
#include <cuda_runtime.h>
#include <cstdint>

#define D    64
#define BM   128
#define BN   256
#define PAD  68          // words; 68 mod 32 == 4 -> conflict-free fragment LDS
#define MAXROWS 8192

// ---------------------------------------------------------------------------
__device__ __forceinline__ uint32_t f2tf32(float f) {
    uint32_t u;
    asm("cvt.rna.tf32.f32 %0, %1;" : "=r"(u) : "f"(f));
    return u;
}

// ---------------------------------------------------------------------------
// Fused single kernel: one 128x256 tile per CTA, 8 warps (2 x 4),
// warp tile 64x64. cross = x1 . x2^T via mma.sync m16n8k8 tf32.
// Row norms computed in-CTA from the staged tf32-rounded tiles
// (self-consistent: result is exactly ||x~ - y~||^2).
// ---------------------------------------------------------------------------
__global__ __launch_bounds__(256, 1)
void dist_kernel(const float* __restrict__ x1, const float* __restrict__ x2,
                 float* __restrict__ out, int M) {
    extern __shared__ uint32_t smem[];
    uint32_t* sa = smem;              // [BM][PAD] tf32 bits
    uint32_t* sb = smem + BM * PAD;   // [BN][PAD]
    float* snrm = (float*)(smem + (BM + BN) * PAD);  // [BM + BN]: A norms, B norms

    const int n0  = blockIdx.y * BM;
    const int m0  = blockIdx.x * BN;
    const int tid = threadIdx.x;
    const int wid = tid >> 5;
    const int lane = tid & 31;
    const int wm = wid >> 2;          // 0..1 : 64-row band
    const int wn = wid & 3;           // 0..3 : 64-col band
    const int g  = lane >> 2;         // 0..7
    const int q  = lane & 3;          // 0..3

    // ---- stage tiles: gmem float4 -> tf32(RNA) -> smem ----
    {
#pragma unroll
        for (int it = 0; it < 8; ++it) {          // A: 2048 float4 slots
            int idx = tid + it * 256;
            int r = idx >> 4, c4 = (idx & 15) * 4;
            float4 v = *(const float4*)(x1 + (size_t)(n0 + r) * D + c4);
            *(uint4*)(sa + r * PAD + c4) =
                make_uint4(f2tf32(v.x), f2tf32(v.y), f2tf32(v.z), f2tf32(v.w));
        }
#pragma unroll
        for (int it = 0; it < 16; ++it) {         // B: 4096 float4 slots
            int idx = tid + it * 256;
            int r = idx >> 4, c4 = (idx & 15) * 4;
            float4 v = *(const float4*)(x2 + (size_t)(m0 + r) * D + c4);
            *(uint4*)(sb + r * PAD + c4) =
                make_uint4(f2tf32(v.x), f2tf32(v.y), f2tf32(v.z), f2tf32(v.w));
        }
    }
    __syncthreads();

    // ---- in-CTA row norms from staged tf32 values ----
    {
        // every thread: one B row; threads < 128 additionally one A row
        const uint32_t* rowb = sb + tid * PAD;
        float s = 0.f;
#pragma unroll
        for (int k4 = 0; k4 < 16; ++k4) {
            uint4 u = *(const uint4*)(rowb + k4 * 4);
            float a = __uint_as_float(u.x), b = __uint_as_float(u.y);
            float c = __uint_as_float(u.z), d = __uint_as_float(u.w);
            s = fmaf(a, a, s); s = fmaf(b, b, s);
            s = fmaf(c, c, s); s = fmaf(d, d, s);
        }
        snrm[BM + tid] = s;
        if (tid < BM) {
            const uint32_t* rowa = sa + tid * PAD;
            float t = 0.f;
#pragma unroll
            for (int k4 = 0; k4 < 16; ++k4) {
                uint4 u = *(const uint4*)(rowa + k4 * 4);
                float a = __uint_as_float(u.x), b = __uint_as_float(u.y);
                float c = __uint_as_float(u.z), d = __uint_as_float(u.w);
                t = fmaf(a, a, t); t = fmaf(b, b, t);
                t = fmaf(c, c, t); t = fmaf(d, d, t);
            }
            snrm[tid] = t;
        }
    }

    float acc[4][8][4];               // [mf][nf][c0..c3]
#pragma unroll
    for (int i = 0; i < 4; ++i)
#pragma unroll
        for (int j = 0; j < 8; ++j)
#pragma unroll
            for (int c = 0; c < 4; ++c) acc[i][j][c] = 0.f;

    __syncthreads();

    // ---- K loop: 8 steps of k=8 ----
#pragma unroll
    for (int ks = 0; ks < 8; ++ks) {
        const int kb = ks * 8;

        // B fragments: col n = wn*64 + nf*8 + g, k = kb + q (+4)
        uint32_t bfr[8][2];
#pragma unroll
        for (int nf = 0; nf < 8; ++nf) {
            const uint32_t* bp = sb + (wn * 64 + nf * 8 + g) * PAD + kb + q;
            bfr[nf][0] = bp[0];
            bfr[nf][1] = bp[4];
        }

#pragma unroll
        for (int mf = 0; mf < 4; ++mf) {
            const int r = wm * 64 + mf * 16 + g;
            const uint32_t* ap = sa + r * PAD + kb + q;
            uint32_t a0 = ap[0];
            uint32_t a1 = ap[8 * PAD];
            uint32_t a2 = ap[4];
            uint32_t a3 = ap[8 * PAD + 4];
#pragma unroll
            for (int nf = 0; nf < 8; ++nf) {
                asm volatile(
                    "mma.sync.aligned.m16n8k8.row.col.f32.tf32.tf32.f32 "
                    "{%0,%1,%2,%3}, {%4,%5,%6,%7}, {%8,%9}, {%0,%1,%2,%3};"
                    : "+f"(acc[mf][nf][0]), "+f"(acc[mf][nf][1]),
                      "+f"(acc[mf][nf][2]), "+f"(acc[mf][nf][3])
                    : "r"(a0), "r"(a1), "r"(a2), "r"(a3),
                      "r"(bfr[nf][0]), "r"(bfr[nf][1]));
            }
        }
    }

    // ---- epilogue: d2 = max(s1 + s2 - 2*cross, 0), streaming stores ----
    const float* nrmA = snrm;
    const float* nrmB = snrm + BM;
#pragma unroll
    for (int mf = 0; mf < 4; ++mf) {
        const int rloc = wm * 64 + mf * 16 + g;
        const float s1a = nrmA[rloc];
        const float s1b = nrmA[rloc + 8];
        float* orow_a = out + (size_t)(n0 + rloc) * M + m0;
        float* orow_b = orow_a + (size_t)8 * M;
#pragma unroll
        for (int nf = 0; nf < 8; ++nf) {
            const int cidx = wn * 64 + nf * 8 + q * 2;
            const float2 s2 = *(const float2*)&nrmB[cidx];
            float2 ra, rb;
            ra.x = fmaxf(fmaf(-2.f, acc[mf][nf][0], s1a + s2.x), 0.f);
            ra.y = fmaxf(fmaf(-2.f, acc[mf][nf][1], s1a + s2.y), 0.f);
            rb.x = fmaxf(fmaf(-2.f, acc[mf][nf][2], s1b + s2.x), 0.f);
            rb.y = fmaxf(fmaf(-2.f, acc[mf][nf][3], s1b + s2.y), 0.f);
            __stcs((float2*)(orow_a + cidx), ra);
            __stcs((float2*)(orow_b + cidx), rb);
        }
    }
}

// ---------------------------------------------------------------------------
extern "C" void kernel_launch(void* const* d_in, const int* in_sizes, int n_in,
                              void* d_out, int out_size) {
    const float* x1 = (const float*)d_in[0];
    const float* x2 = (const float*)d_in[1];
    float* out = (float*)d_out;

    const int N = in_sizes[0] / D;   // 8192
    const int M = in_sizes[1] / D;   // 8192

    const int smem_bytes = (BM + BN) * PAD * sizeof(uint32_t)
                         + (BM + BN) * sizeof(float);   // 104448 + 1536 = 105984
    cudaFuncSetAttribute(dist_kernel,
                         cudaFuncAttributeMaxDynamicSharedMemorySize, smem_bytes);

    dim3 grid(M / BN, N / BM);
    dist_kernel<<<grid, 256, smem_bytes>>>(x1, x2, out, M);
}

// round 8
// speedup vs baseline: 1.0562x; 1.0562x over previous
#include <cuda_runtime.h>
#include <cstdint>

#define D    64
#define BM   128
#define BN   128
#define PAD  68          // words; 68 mod 32 == 4 -> conflict-free fragment LDS
#define MAXROWS 8192

// ---------------------------------------------------------------------------
__device__ __forceinline__ uint32_t f2tf32(float f) {
    uint32_t u;
    asm("cvt.rna.tf32.f32 %0, %1;" : "=r"(u) : "f"(f));
    return u;
}

// ---------------------------------------------------------------------------
// Fused single kernel: 128x128 tile per CTA, 4 warps (2 x 2), warp tile 64x64.
// 128 threads/CTA keeps regs/CTA low enough for 2 CTAs/SM (latency overlap)
// while warp tile 64x64 keeps fragment-LDS bytes/output at 8.
// cross = x1 . x2^T via mma.sync m16n8k8 tf32; row norms computed in-CTA from
// staged tf32-rounded tiles (self-consistent ||x~ - y~||^2).
// ---------------------------------------------------------------------------
__global__ __launch_bounds__(128, 2)
void dist_kernel(const float* __restrict__ x1, const float* __restrict__ x2,
                 float* __restrict__ out, int M) {
    extern __shared__ uint32_t smem[];
    uint32_t* sa = smem;              // [BM][PAD] tf32 bits
    uint32_t* sb = smem + BM * PAD;   // [BN][PAD]
    float* snrm = (float*)(smem + (BM + BN) * PAD);  // [BM + BN]

    const int n0  = blockIdx.y * BM;
    const int m0  = blockIdx.x * BN;
    const int tid = threadIdx.x;
    const int wid = tid >> 5;
    const int lane = tid & 31;
    const int wm = wid >> 1;          // 0..1 : 64-row band
    const int wn = wid & 1;           // 0..1 : 64-col band
    const int g  = lane >> 2;         // 0..7
    const int q  = lane & 3;          // 0..3

    // ---- stage tiles: gmem float4 -> tf32(RNA) -> smem ----
    {
#pragma unroll
        for (int it = 0; it < 16; ++it) {         // A: 2048 float4 slots
            int idx = tid + it * 128;
            int r = idx >> 4, c4 = (idx & 15) * 4;
            float4 v = *(const float4*)(x1 + (size_t)(n0 + r) * D + c4);
            *(uint4*)(sa + r * PAD + c4) =
                make_uint4(f2tf32(v.x), f2tf32(v.y), f2tf32(v.z), f2tf32(v.w));
        }
#pragma unroll
        for (int it = 0; it < 16; ++it) {         // B: 2048 float4 slots
            int idx = tid + it * 128;
            int r = idx >> 4, c4 = (idx & 15) * 4;
            float4 v = *(const float4*)(x2 + (size_t)(m0 + r) * D + c4);
            *(uint4*)(sb + r * PAD + c4) =
                make_uint4(f2tf32(v.x), f2tf32(v.y), f2tf32(v.z), f2tf32(v.w));
        }
    }
    __syncthreads();

    // ---- in-CTA row norms from staged tf32 values (1 A row + 1 B row each) ----
    {
        const uint32_t* rowa = sa + tid * PAD;
        const uint32_t* rowb = sb + tid * PAD;
        float t = 0.f, s = 0.f;
#pragma unroll
        for (int k4 = 0; k4 < 16; ++k4) {
            uint4 ua = *(const uint4*)(rowa + k4 * 4);
            uint4 ub = *(const uint4*)(rowb + k4 * 4);
            float a0 = __uint_as_float(ua.x), a1 = __uint_as_float(ua.y);
            float a2 = __uint_as_float(ua.z), a3 = __uint_as_float(ua.w);
            float b0 = __uint_as_float(ub.x), b1 = __uint_as_float(ub.y);
            float b2 = __uint_as_float(ub.z), b3 = __uint_as_float(ub.w);
            t = fmaf(a0, a0, t); t = fmaf(a1, a1, t);
            t = fmaf(a2, a2, t); t = fmaf(a3, a3, t);
            s = fmaf(b0, b0, s); s = fmaf(b1, b1, s);
            s = fmaf(b2, b2, s); s = fmaf(b3, b3, s);
        }
        snrm[tid] = t;
        snrm[BM + tid] = s;
    }

    float acc[4][8][4];               // [mf][nf][c0..c3]
#pragma unroll
    for (int i = 0; i < 4; ++i)
#pragma unroll
        for (int j = 0; j < 8; ++j)
#pragma unroll
            for (int c = 0; c < 4; ++c) acc[i][j][c] = 0.f;

    __syncthreads();

    // ---- K loop: 8 steps of k=8 ----
#pragma unroll
    for (int ks = 0; ks < 8; ++ks) {
        const int kb = ks * 8;

        // B fragments: col n = wn*64 + nf*8 + g, k = kb + q (+4)
        uint32_t bfr[8][2];
#pragma unroll
        for (int nf = 0; nf < 8; ++nf) {
            const uint32_t* bp = sb + (wn * 64 + nf * 8 + g) * PAD + kb + q;
            bfr[nf][0] = bp[0];
            bfr[nf][1] = bp[4];
        }

#pragma unroll
        for (int mf = 0; mf < 4; ++mf) {
            const int r = wm * 64 + mf * 16 + g;
            const uint32_t* ap = sa + r * PAD + kb + q;
            uint32_t a0 = ap[0];
            uint32_t a1 = ap[8 * PAD];
            uint32_t a2 = ap[4];
            uint32_t a3 = ap[8 * PAD + 4];
#pragma unroll
            for (int nf = 0; nf < 8; ++nf) {
                asm volatile(
                    "mma.sync.aligned.m16n8k8.row.col.f32.tf32.tf32.f32 "
                    "{%0,%1,%2,%3}, {%4,%5,%6,%7}, {%8,%9}, {%0,%1,%2,%3};"
                    : "+f"(acc[mf][nf][0]), "+f"(acc[mf][nf][1]),
                      "+f"(acc[mf][nf][2]), "+f"(acc[mf][nf][3])
                    : "r"(a0), "r"(a1), "r"(a2), "r"(a3),
                      "r"(bfr[nf][0]), "r"(bfr[nf][1]));
            }
        }
    }

    // ---- epilogue: d2 = max(s1 + s2 - 2*cross, 0), streaming stores ----
    const float* nrmA = snrm;
    const float* nrmB = snrm + BM;
#pragma unroll
    for (int mf = 0; mf < 4; ++mf) {
        const int rloc = wm * 64 + mf * 16 + g;
        const float s1a = nrmA[rloc];
        const float s1b = nrmA[rloc + 8];
        float* orow_a = out + (size_t)(n0 + rloc) * M + m0;
        float* orow_b = orow_a + (size_t)8 * M;
#pragma unroll
        for (int nf = 0; nf < 8; ++nf) {
            const int cidx = wn * 64 + nf * 8 + q * 2;
            const float2 s2 = *(const float2*)&nrmB[cidx];
            float2 ra, rb;
            ra.x = fmaxf(fmaf(-2.f, acc[mf][nf][0], s1a + s2.x), 0.f);
            ra.y = fmaxf(fmaf(-2.f, acc[mf][nf][1], s1a + s2.y), 0.f);
            rb.x = fmaxf(fmaf(-2.f, acc[mf][nf][2], s1b + s2.x), 0.f);
            rb.y = fmaxf(fmaf(-2.f, acc[mf][nf][3], s1b + s2.y), 0.f);
            __stcs((float2*)(orow_a + cidx), ra);
            __stcs((float2*)(orow_b + cidx), rb);
        }
    }
}

// ---------------------------------------------------------------------------
extern "C" void kernel_launch(void* const* d_in, const int* in_sizes, int n_in,
                              void* d_out, int out_size) {
    const float* x1 = (const float*)d_in[0];
    const float* x2 = (const float*)d_in[1];
    float* out = (float*)d_out;

    const int N = in_sizes[0] / D;   // 8192
    const int M = in_sizes[1] / D;   // 8192

    const int smem_bytes = (BM + BN) * PAD * sizeof(uint32_t)
                         + (BM + BN) * sizeof(float);   // 69632 + 1024 = 70656
    cudaFuncSetAttribute(dist_kernel,
                         cudaFuncAttributeMaxDynamicSharedMemorySize, smem_bytes);

    dim3 grid(M / BN, N / BM);
    dist_kernel<<<grid, 128, smem_bytes>>>(x1, x2, out, M);
}